// round 9
// baseline (speedup 1.0000x reference)
#include <cuda_runtime.h>
#include <cuda_bf16.h>
#include <math.h>
#include <stdint.h>
#include <string.h>

// ---------------------------------------------------------------------------
// ChannelBlock: B=32, N=784 (28x28), C=384, heads=8, hd=48, MLP hidden=1536
// bf16 mma.sync GEMMs (256x128 CTA, 64x64 warp tiles, 2-stage cp.async),
// f32x2-packed attnA, tiled cpe_ln, 16-token attnB.
// ---------------------------------------------------------------------------

#define Bsz   32
#define Ntok  784
#define Cdim  384
#define NT    (Bsz * Ntok)     // 25088
#define H3    (3 * Cdim)       // 1152
#define HID   1536
#define NH    8
#define HD    48
#define NCHUNK 7               // attnA token chunks (112 each)

typedef __nv_bfloat16 bf16;
typedef unsigned long long ull;

// scratch (static device memory; no allocation anywhere)
__device__ float g_xa  [(size_t)NT * Cdim];
__device__ bf16  g_ln  [(size_t)NT * Cdim];
__device__ float g_qkv [(size_t)NT * H3];
__device__ float g_attn[(size_t)NCHUNK * Bsz * NH * HD * HD];  // partial logits
__device__ float g_attn2[(size_t)Bsz * NH * HD * HD];          // softmaxed
__device__ bf16  g_att [(size_t)NT * Cdim];
__device__ float g_xb  [(size_t)NT * Cdim];
__device__ bf16  g_h   [(size_t)NT * HID];
// bf16 weights: qkv | proj | fc1 | fc2
#define W_QKV 0
#define W_PROJ (H3 * Cdim)
#define W_FC1  (W_PROJ + Cdim * Cdim)
#define W_FC2  (W_FC1 + HID * Cdim)
#define W_TOT  (W_FC2 + Cdim * HID)
__device__ bf16  g_wbf [(size_t)W_TOT];

// single launch: convert all 4 weight matrices to bf16
__global__ void cvt_all_kernel(const float* __restrict__ qkv_w,
                               const float* __restrict__ proj_w,
                               const float* __restrict__ fc1_w,
                               const float* __restrict__ fc2_w,
                               bf16* __restrict__ out)
{
    int i = blockIdx.x * blockDim.x + threadIdx.x;
    if (i >= W_TOT) return;
    float v;
    if (i < W_PROJ)      v = qkv_w[i];
    else if (i < W_FC1)  v = proj_w[i - W_PROJ];
    else if (i < W_FC2)  v = fc1_w[i - W_FC1];
    else                 v = fc2_w[i - W_FC2];
    out[i] = __float2bfloat16(v);
}

// ---------------------------------------------------------------------------
// Tiled fused cpe + LN (unchanged from R8).
// ---------------------------------------------------------------------------
#define TJ 7
__global__ __launch_bounds__(Cdim)
void cpe_ln_kernel(const float* __restrict__ x,
                   const float* __restrict__ w,
                   const float* __restrict__ bias,
                   const float* __restrict__ lng,
                   const float* __restrict__ lnb,
                   float* __restrict__ y,
                   bf16* __restrict__ yln)
{
    __shared__ float tile[3][TJ + 2][Cdim];
    __shared__ float redS[12][TJ], redQ[12][TJ];
    __shared__ float stats[TJ][2];

    int c  = threadIdx.x;
    int jg = blockIdx.x;
    int i  = blockIdx.y;
    int b  = blockIdx.z;
    int j0 = jg * TJ;

    const float* xb = x + (size_t)b * Ntok * Cdim;

#pragma unroll
    for (int s = 0; s < 3 * (TJ + 2); s++) {
        int ri = s / (TJ + 2) + i - 1;
        int cj = s % (TJ + 2) + j0 - 1;
        float v = 0.f;
        if (ri >= 0 && ri < 28 && cj >= 0 && cj < 28)
            v = xb[(size_t)(ri * 28 + cj) * Cdim + c];
        tile[s / (TJ + 2)][s % (TJ + 2)][c] = v;
    }
    __syncthreads();

    const float* wc = w + c * 9;
    float wr[9];
#pragma unroll
    for (int q = 0; q < 9; q++) wr[q] = wc[q];
    float bs = bias[c];

    float val[TJ];
#pragma unroll
    for (int jt = 0; jt < TJ; jt++) {
        float acc = bs;
#pragma unroll
        for (int di = 0; di < 3; di++)
#pragma unroll
            for (int dj = 0; dj < 3; dj++)
                acc += wr[di * 3 + dj] * tile[di][jt + dj][c];
        val[jt] = tile[1][1 + jt][c] + acc;
    }

    int warp = c >> 5, lane = c & 31;
#pragma unroll
    for (int jt = 0; jt < TJ; jt++) {
        float s = val[jt], q = val[jt] * val[jt];
#pragma unroll
        for (int o = 16; o; o >>= 1) {
            s += __shfl_xor_sync(0xffffffffu, s, o);
            q += __shfl_xor_sync(0xffffffffu, q, o);
        }
        if (lane == 0) { redS[warp][jt] = s; redQ[warp][jt] = q; }
    }
    __syncthreads();
    if (c < TJ) {
        float ts = 0.f, tq = 0.f;
#pragma unroll
        for (int k = 0; k < 12; k++) { ts += redS[k][c]; tq += redQ[k][c]; }
        float mean = ts * (1.f / Cdim);
        float var  = tq * (1.f / Cdim) - mean * mean;
        stats[c][0] = mean;
        stats[c][1] = rsqrtf(var + 1e-5f);
    }
    __syncthreads();

    float gg = lng[c], bb = lnb[c];
#pragma unroll
    for (int jt = 0; jt < TJ; jt++) {
        size_t idx = ((size_t)b * Ntok + i * 28 + j0 + jt) * Cdim + c;
        float v = val[jt];
        y[idx] = v;
        yln[idx] = __float2bfloat16((v - stats[jt][0]) * stats[jt][1] * gg + bb);
    }
}

// ---------------------------------------------------------------------------
// bf16 GEMM, NT form: C[m,n] = sum_k A[m,k] * W[n,k] (+ epilogue)
// CTA 256(M) x 128(N), BK=32, 256 threads = 8 warps (4m x 2n), warp tile 64x64.
// 2-stage cp.async pipeline, 48KB static smem, ldmatrix fragments.
// EPI: 0 = none -> fp32 ; 2 = +bias + GELU -> bf16 ; 3 = +bias+res -> fp32
// ---------------------------------------------------------------------------
#define BMg 256
#define BNg 128
#define BK 32
#define ASTG (BMg * 64)                // 16384 B per A stage (64B rows)
#define STG_BYTES (ASTG + BNg * 64)    // 24576 B (A + B)

__device__ __forceinline__ void cp16(unsigned saddr, const void* g)
{
    asm volatile("cp.async.cg.shared.global [%0], [%1], 16;\n" :: "r"(saddr), "l"(g));
}
__device__ __forceinline__ void ldsm4(uint32_t& r0, uint32_t& r1, uint32_t& r2,
                                      uint32_t& r3, uint32_t a)
{
    asm volatile("ldmatrix.sync.aligned.m8n8.x4.shared.b16 {%0,%1,%2,%3}, [%4];"
                 : "=r"(r0), "=r"(r1), "=r"(r2), "=r"(r3) : "r"(a));
}

template<int EPI, int K>
__global__ __launch_bounds__(256, 1)
void gemm_bf16(const bf16* __restrict__ A, const bf16* __restrict__ W,
               const float* __restrict__ bias, const float* __restrict__ res,
               void* __restrict__ Cout, int M, int N)
{
    __shared__ alignas(128) char sm[2 * STG_BYTES];   // 48 KB
    uint32_t sb = (uint32_t)__cvta_generic_to_shared(sm);

    int tid = threadIdx.x;
    int w = tid >> 5, l = tid & 31;
    int row0 = blockIdx.y * BMg;
    int col0 = blockIdx.x * BNg;
    int wm = (w >> 1) * 64;            // 4 m-groups
    int wn = (w & 1) * 64;             // 2 n-groups
    int g = l >> 2, t = l & 3;

    // --- ldmatrix address precompute ---
    int jj  = l >> 3;
    int rlo = l & 7;
    int rowA_in = (jj & 1) * 8 + rlo;
    int cA = jj >> 1;
    uint32_t aoff[4], axr[4];
#pragma unroll
    for (int mi = 0; mi < 4; mi++) {
        int rA = wm + mi * 16 + rowA_in;
        aoff[mi] = (uint32_t)rA * 64;
        axr[mi]  = (uint32_t)(((rA >> 1) & 3) << 4);
    }
    int rowB_in = (jj >> 1) * 8 + rlo;
    int cB = jj & 1;
    uint32_t boff[4], bxr[4];
#pragma unroll
    for (int p = 0; p < 4; p++) {
        int rB = wn + p * 16 + rowB_in;
        boff[p] = (uint32_t)(ASTG + rB * 64);
        bxr[p]  = (uint32_t)(((rB >> 1) & 3) << 4);
    }

    float acc[4][8][4];
#pragma unroll
    for (int mi = 0; mi < 4; mi++)
#pragma unroll
        for (int ni = 0; ni < 8; ni++)
#pragma unroll
            for (int r = 0; r < 4; r++) acc[mi][ni][r] = 0.f;

    constexpr int NS = K / BK;

    // loader: A 1024 chunks (4/thread), B 512 chunks (2/thread)
    auto load_stage = [&](int s) {
        uint32_t tb = sb + (s & 1) * STG_BYTES;
        int kt = s * BK;
        const bf16* Ab = A + (size_t)row0 * K + kt;
        const bf16* Wb = W + (size_t)col0 * K + kt;
#pragma unroll
        for (int i = 0; i < 4; i++) {
            int id = tid + i * 256;        // 0..1023
            int r = id >> 2, c = id & 3;
            int cs = c ^ ((r >> 1) & 3);
            cp16(tb + r * 64 + cs * 16, Ab + (size_t)r * K + c * 8);
        }
#pragma unroll
        for (int i = 0; i < 2; i++) {
            int id = tid + i * 256;        // 0..511
            int r = id >> 2, c = id & 3;
            int cs = c ^ ((r >> 1) & 3);
            cp16(tb + ASTG + r * 64 + cs * 16, Wb + (size_t)r * K + c * 8);
        }
    };

    load_stage(0);
    asm volatile("cp.async.commit_group;\n");

#pragma unroll 2
    for (int s = 0; s < NS; s++) {
        if (s + 1 < NS) {
            load_stage(s + 1);
            asm volatile("cp.async.commit_group;\n");
            asm volatile("cp.async.wait_group 1;\n");
        } else {
            asm volatile("cp.async.wait_group 0;\n");
        }
        __syncthreads();

        uint32_t stb = sb + (s & 1) * STG_BYTES;
#pragma unroll
        for (int kk = 0; kk < 2; kk++) {
            uint32_t c0 = kk * 2;
            uint32_t af[4][4], bq[4][4];
#pragma unroll
            for (int mi = 0; mi < 4; mi++)
                ldsm4(af[mi][0], af[mi][1], af[mi][2], af[mi][3],
                      stb + aoff[mi] + ((((c0 + cA) << 4)) ^ axr[mi]));
#pragma unroll
            for (int p = 0; p < 4; p++)
                ldsm4(bq[p][0], bq[p][1], bq[p][2], bq[p][3],
                      stb + boff[p] + ((((c0 + cB) << 4)) ^ bxr[p]));

#pragma unroll
            for (int mi = 0; mi < 4; mi++)
#pragma unroll
                for (int ni = 0; ni < 8; ni++) {
                    int p = ni >> 1, q = ni & 1;
                    asm volatile(
                        "mma.sync.aligned.m16n8k16.row.col.f32.bf16.bf16.f32 "
                        "{%0,%1,%2,%3}, {%4,%5,%6,%7}, {%8,%9}, {%0,%1,%2,%3};"
                        : "+f"(acc[mi][ni][0]), "+f"(acc[mi][ni][1]),
                          "+f"(acc[mi][ni][2]), "+f"(acc[mi][ni][3])
                        : "r"(af[mi][0]), "r"(af[mi][1]), "r"(af[mi][2]), "r"(af[mi][3]),
                          "r"(bq[p][2 * q]), "r"(bq[p][2 * q + 1]));
                }
        }
        __syncthreads();   // protect buffer (s&1) before it is reloaded
    }

    // ---- epilogue: float2 / bfloat162 stores ----
#pragma unroll
    for (int mi = 0; mi < 4; mi++) {
#pragma unroll
        for (int ni = 0; ni < 8; ni++) {
            int col = col0 + wn + ni * 8 + 2 * t;
#pragma unroll
            for (int half = 0; half < 2; half++) {
                int row = row0 + wm + mi * 16 + g + half * 8;
                size_t idx = (size_t)row * N + col;
                float v0 = acc[mi][ni][2 * half];
                float v1 = acc[mi][ni][2 * half + 1];
                if (EPI == 0) {
                    *(float2*)&((float*)Cout)[idx] = make_float2(v0, v1);
                } else if (EPI == 2) {
                    float2 bv = *(const float2*)&bias[col];
                    v0 += bv.x; v1 += bv.y;
                    v0 = 0.5f * v0 * (1.f + erff(v0 * 0.7071067811865475f));
                    v1 = 0.5f * v1 * (1.f + erff(v1 * 0.7071067811865475f));
                    __nv_bfloat162 pk;
                    pk.x = __float2bfloat16(v0);
                    pk.y = __float2bfloat16(v1);
                    *(__nv_bfloat162*)&((bf16*)Cout)[idx] = pk;
                } else {
                    float2 bv = *(const float2*)&bias[col];
                    float2 rv = *(const float2*)&res[idx];
                    v0 += bv.x + rv.x; v1 += bv.y + rv.y;
                    *(float2*)&((float*)Cout)[idx] = make_float2(v0, v1);
                }
            }
        }
    }
}

// ---------------------------------------------------------------------------
// Channel attention stage A: per (bh, chunk) partial (k*s)^T v over 112 tokens.
// 192 threads (16 ty x 12 tx), thread tile 3 rows x 4 cols, packed f32x2 FMA.
// Per-lane fp32 fma order identical to scalar loop -> bit-identical results.
// ---------------------------------------------------------------------------
__global__ __launch_bounds__(192)
void attnA_partial(const float* __restrict__ qkv, float* __restrict__ partial)
{
    __shared__ float2 ks2[16][HD];   // k duplicated into both lanes
    __shared__ float  vs [16][HD];

    int bh = blockIdx.x;
    int b = bh >> 3, h = bh & 7;
    int chunk = blockIdx.y;
    int nstart = chunk * 112;
    int tid = threadIdx.x;
    int tx = tid % 12, ty = tid / 12;     // ty 0..15
    const float scale = 0.14433756729740643f;   // 48^-0.5

    ull acc[3][2];
#pragma unroll
    for (int i = 0; i < 3; i++) { acc[i][0] = 0ull; acc[i][1] = 0ull; }

    const float* base = qkv + (size_t)b * Ntok * H3 + h * HD;

    for (int n0 = nstart; n0 < nstart + 112; n0 += 16) {
        // load 16 tokens x 48 d: 768 elems, 192 threads -> 4 iters
#pragma unroll
        for (int it = 0; it < 4; it++) {
            int idx = tid + it * 192;
            int nn = idx / HD, d = idx - nn * HD;
            const float* r = base + (size_t)(n0 + nn) * H3;
            float kv = r[Cdim + d] * scale;
            ks2[nn][d] = make_float2(kv, kv);
            vs[nn][d]  = r[2 * Cdim + d];
        }
        __syncthreads();
#pragma unroll
        for (int nn = 0; nn < 16; nn++) {
            ull k0 = *(const ull*)&ks2[nn][ty * 3 + 0];
            ull k1 = *(const ull*)&ks2[nn][ty * 3 + 1];
            ull k2 = *(const ull*)&ks2[nn][ty * 3 + 2];
            ull v0 = *(const ull*)&vs[nn][tx * 4];
            ull v1 = *(const ull*)&vs[nn][tx * 4 + 2];
            asm("fma.rn.f32x2 %0, %1, %2, %0;" : "+l"(acc[0][0]) : "l"(k0), "l"(v0));
            asm("fma.rn.f32x2 %0, %1, %2, %0;" : "+l"(acc[0][1]) : "l"(k0), "l"(v1));
            asm("fma.rn.f32x2 %0, %1, %2, %0;" : "+l"(acc[1][0]) : "l"(k1), "l"(v0));
            asm("fma.rn.f32x2 %0, %1, %2, %0;" : "+l"(acc[1][1]) : "l"(k1), "l"(v1));
            asm("fma.rn.f32x2 %0, %1, %2, %0;" : "+l"(acc[2][0]) : "l"(k2), "l"(v0));
            asm("fma.rn.f32x2 %0, %1, %2, %0;" : "+l"(acc[2][1]) : "l"(k2), "l"(v1));
        }
        __syncthreads();
    }

    float* o = partial + ((size_t)chunk * (Bsz * NH) + bh) * (HD * HD);
#pragma unroll
    for (int i = 0; i < 3; i++)
#pragma unroll
        for (int q = 0; q < 2; q++) {
            float2 f;
            memcpy(&f, &acc[i][q], 8);
            int d = ty * 3 + i, e = tx * 4 + 2 * q;
            o[d * HD + e]     = f.x;
            o[d * HD + e + 1] = f.y;
        }
}

// softmax over last dim of 48x48 logits after summing 7 partials.
__global__ __launch_bounds__(256)
void attnA_softmax(const float* __restrict__ partial, float* __restrict__ attn_out)
{
    int idx = blockIdx.x * 256 + threadIdx.x;     // bh*48 + d
    if (idx >= Bsz * NH * HD) return;
    int bh = idx / HD, d = idx - bh * HD;

    float row[HD];
#pragma unroll
    for (int e = 0; e < HD; e++) row[e] = 0.f;
#pragma unroll
    for (int ch = 0; ch < NCHUNK; ch++) {
        const float* p = partial + ((size_t)ch * (Bsz * NH) + bh) * (HD * HD) + d * HD;
#pragma unroll
        for (int e = 0; e < HD; e++) row[e] += p[e];
    }
    float m = -1e30f;
#pragma unroll
    for (int e = 0; e < HD; e++) m = fmaxf(m, row[e]);
    float s = 0.f;
#pragma unroll
    for (int e = 0; e < HD; e++) { row[e] = expf(row[e] - m); s += row[e]; }
    float inv = 1.f / s;
    float* o = attn_out + (size_t)bh * (HD * HD) + d * HD;
#pragma unroll
    for (int e = 0; e < HD; e++) o[e] = row[e] * inv;
}

// ---------------------------------------------------------------------------
// Channel attention stage B: 16 tokens per block (each thread does 2 tokens).
// out[b,n,h*48+d] = sum_e attn[d,e] * q[b,n,h,e]
// ---------------------------------------------------------------------------
__global__ __launch_bounds__(384)
void attnB_kernel(const float* __restrict__ qkv, const float* __restrict__ attn,
                  bf16* __restrict__ out)
{
    __shared__ float at[48 * 49];
    __shared__ float qs[16][48];

    int bh = blockIdx.x;
    int b = bh >> 3, h = bh & 7;
    int n0 = blockIdx.y * 16;
    int tid = threadIdx.x;

    const float* ab = attn + (size_t)bh * (HD * HD);
#pragma unroll
    for (int it = 0; it < 6; it++) {
        int idx = tid + it * 384;
        int d = idx / HD, e = idx - d * HD;
        at[d * 49 + e] = ab[idx];
    }
    int nl = tid / HD;           // 0..7
    int d  = tid - nl * HD;      // 0..47
    qs[nl][d]     = qkv[((size_t)b * Ntok + n0 + nl) * H3 + h * HD + d];
    qs[nl + 8][d] = qkv[((size_t)b * Ntok + n0 + nl + 8) * H3 + h * HD + d];
    __syncthreads();

    float acc0 = 0.f, acc1 = 0.f;
#pragma unroll
    for (int e = 0; e < HD; e++) {
        float a = at[d * 49 + e];
        acc0 = fmaf(a, qs[nl][e], acc0);
        acc1 = fmaf(a, qs[nl + 8][e], acc1);
    }

    out[((size_t)b * Ntok + n0 + nl) * Cdim + h * HD + d]     = __float2bfloat16(acc0);
    out[((size_t)b * Ntok + n0 + nl + 8) * Cdim + h * HD + d] = __float2bfloat16(acc1);
}

// ---------------------------------------------------------------------------
// Launch
// ---------------------------------------------------------------------------
extern "C" void kernel_launch(void* const* d_in, const int* in_sizes, int n_in,
                              void* d_out, int out_size)
{
    const float* x       = (const float*)d_in[0];
    const float* cpe0_w  = (const float*)d_in[3];
    const float* cpe0_b  = (const float*)d_in[4];
    const float* cpe1_w  = (const float*)d_in[5];
    const float* cpe1_b  = (const float*)d_in[6];
    const float* norm1_g = (const float*)d_in[7];
    const float* norm1_b = (const float*)d_in[8];
    const float* qkv_w   = (const float*)d_in[9];
    const float* proj_w  = (const float*)d_in[10];
    const float* proj_b  = (const float*)d_in[11];
    const float* norm2_g = (const float*)d_in[12];
    const float* norm2_b = (const float*)d_in[13];
    const float* fc1_w   = (const float*)d_in[14];
    const float* fc1_b   = (const float*)d_in[15];
    const float* fc2_w   = (const float*)d_in[16];
    const float* fc2_b   = (const float*)d_in[17];
    float* out = (float*)d_out;

    float *xa, *qkvb, *attn, *attn2, *xb;
    bf16 *ln, *att, *hbuf, *wbf;
    cudaGetSymbolAddress((void**)&xa,    g_xa);
    cudaGetSymbolAddress((void**)&ln,    g_ln);
    cudaGetSymbolAddress((void**)&qkvb,  g_qkv);
    cudaGetSymbolAddress((void**)&attn,  g_attn);
    cudaGetSymbolAddress((void**)&attn2, g_attn2);
    cudaGetSymbolAddress((void**)&att,   g_att);
    cudaGetSymbolAddress((void**)&xb,    g_xb);
    cudaGetSymbolAddress((void**)&hbuf,  g_h);
    cudaGetSymbolAddress((void**)&wbf,   g_wbf);

    dim3 cpeGrid(4, 28, Bsz);

    // one launch: convert all weights to bf16
    cvt_all_kernel<<<(W_TOT + 255) / 256, 256>>>(qkv_w, proj_w, fc1_w, fc2_w, wbf);

    // xa = cpe0(x); ln = LN1(xa) [bf16]
    cpe_ln_kernel<<<cpeGrid, Cdim>>>(x, cpe0_w, cpe0_b, norm1_g, norm1_b, xa, ln);
    // qkv = ln1 @ qkv_w^T  (fp32 out)
    gemm_bf16<0, Cdim><<<dim3(H3 / BNg, NT / BMg), 256>>>(ln, wbf + W_QKV, nullptr, nullptr, qkvb, NT, H3);
    // channel attention
    attnA_partial<<<dim3(Bsz * NH, NCHUNK), 192>>>(qkvb, attn);
    attnA_softmax<<<(Bsz * NH * HD + 255) / 256, 256>>>(attn, attn2);
    attnB_kernel<<<dim3(Bsz * NH, Ntok / 16), 384>>>(qkvb, attn2, att);
    // xb = xa + att @ proj_w^T + proj_b  (fp32 out)
    gemm_bf16<3, Cdim><<<dim3(Cdim / BNg, NT / BMg), 256>>>(att, wbf + W_PROJ, proj_b, xa, xb, NT, Cdim);
    // xc = cpe1(xb) -> xa ; ln = LN2(xc) [bf16]
    cpe_ln_kernel<<<cpeGrid, Cdim>>>(xb, cpe1_w, cpe1_b, norm2_g, norm2_b, xa, ln);
    // h = gelu(ln2 @ fc1^T + b1) [bf16 out]
    gemm_bf16<2, Cdim><<<dim3(HID / BNg, NT / BMg), 256>>>(ln, wbf + W_FC1, fc1_b, nullptr, hbuf, NT, HID);
    // out = xc + h @ fc2^T + b2 (fp32 out)
    gemm_bf16<3, HID><<<dim3(Cdim / BNg, NT / BMg), 256>>>(hbuf, wbf + W_FC2, fc2_b, xa, out, NT, Cdim);
}

// round 10
// speedup vs baseline: 1.2351x; 1.2351x over previous
#include <cuda_runtime.h>
#include <cuda_bf16.h>
#include <math.h>
#include <stdint.h>

// ---------------------------------------------------------------------------
// ChannelBlock: B=32, N=784 (28x28), C=384, heads=8, hd=48, MLP hidden=1536
// bf16 mma.sync GEMMs (R8 config: 128x128 CTA, 64x32 warp tiles, 3-stage
// cp.async), tiled cpe_ln, scalar attnA (R8), fused softmax+attnB.
// ---------------------------------------------------------------------------

#define Bsz   32
#define Ntok  784
#define Cdim  384
#define NT    (Bsz * Ntok)     // 25088
#define H3    (3 * Cdim)       // 1152
#define HID   1536
#define NH    8
#define HD    48
#define NCHUNK 7               // attnA token chunks (112 each)

typedef __nv_bfloat16 bf16;

// scratch (static device memory; no allocation anywhere)
__device__ float g_xa  [(size_t)NT * Cdim];
__device__ bf16  g_ln  [(size_t)NT * Cdim];
__device__ float g_qkv [(size_t)NT * H3];
__device__ float g_attn[(size_t)NCHUNK * Bsz * NH * HD * HD];  // partial logits
__device__ bf16  g_att [(size_t)NT * Cdim];
__device__ float g_xb  [(size_t)NT * Cdim];
__device__ bf16  g_h   [(size_t)NT * HID];
// bf16 weights: qkv | proj | fc1 | fc2
#define W_QKV 0
#define W_PROJ (H3 * Cdim)
#define W_FC1  (W_PROJ + Cdim * Cdim)
#define W_FC2  (W_FC1 + HID * Cdim)
#define W_TOT  (W_FC2 + Cdim * HID)
__device__ bf16  g_wbf [(size_t)W_TOT];

// single launch: convert all 4 weight matrices to bf16
__global__ void cvt_all_kernel(const float* __restrict__ qkv_w,
                               const float* __restrict__ proj_w,
                               const float* __restrict__ fc1_w,
                               const float* __restrict__ fc2_w,
                               bf16* __restrict__ out)
{
    int i = blockIdx.x * blockDim.x + threadIdx.x;
    if (i >= W_TOT) return;
    float v;
    if (i < W_PROJ)      v = qkv_w[i];
    else if (i < W_FC1)  v = proj_w[i - W_PROJ];
    else if (i < W_FC2)  v = fc1_w[i - W_FC1];
    else                 v = fc2_w[i - W_FC2];
    out[i] = __float2bfloat16(v);
}

// ---------------------------------------------------------------------------
// Tiled fused cpe + LN (R8).
// ---------------------------------------------------------------------------
#define TJ 7
__global__ __launch_bounds__(Cdim)
void cpe_ln_kernel(const float* __restrict__ x,
                   const float* __restrict__ w,
                   const float* __restrict__ bias,
                   const float* __restrict__ lng,
                   const float* __restrict__ lnb,
                   float* __restrict__ y,
                   bf16* __restrict__ yln)
{
    __shared__ float tile[3][TJ + 2][Cdim];
    __shared__ float redS[12][TJ], redQ[12][TJ];
    __shared__ float stats[TJ][2];

    int c  = threadIdx.x;
    int jg = blockIdx.x;
    int i  = blockIdx.y;
    int b  = blockIdx.z;
    int j0 = jg * TJ;

    const float* xb = x + (size_t)b * Ntok * Cdim;

#pragma unroll
    for (int s = 0; s < 3 * (TJ + 2); s++) {
        int ri = s / (TJ + 2) + i - 1;
        int cj = s % (TJ + 2) + j0 - 1;
        float v = 0.f;
        if (ri >= 0 && ri < 28 && cj >= 0 && cj < 28)
            v = xb[(size_t)(ri * 28 + cj) * Cdim + c];
        tile[s / (TJ + 2)][s % (TJ + 2)][c] = v;
    }
    __syncthreads();

    const float* wc = w + c * 9;
    float wr[9];
#pragma unroll
    for (int q = 0; q < 9; q++) wr[q] = wc[q];
    float bs = bias[c];

    float val[TJ];
#pragma unroll
    for (int jt = 0; jt < TJ; jt++) {
        float acc = bs;
#pragma unroll
        for (int di = 0; di < 3; di++)
#pragma unroll
            for (int dj = 0; dj < 3; dj++)
                acc += wr[di * 3 + dj] * tile[di][jt + dj][c];
        val[jt] = tile[1][1 + jt][c] + acc;
    }

    int warp = c >> 5, lane = c & 31;
#pragma unroll
    for (int jt = 0; jt < TJ; jt++) {
        float s = val[jt], q = val[jt] * val[jt];
#pragma unroll
        for (int o = 16; o; o >>= 1) {
            s += __shfl_xor_sync(0xffffffffu, s, o);
            q += __shfl_xor_sync(0xffffffffu, q, o);
        }
        if (lane == 0) { redS[warp][jt] = s; redQ[warp][jt] = q; }
    }
    __syncthreads();
    if (c < TJ) {
        float ts = 0.f, tq = 0.f;
#pragma unroll
        for (int k = 0; k < 12; k++) { ts += redS[k][c]; tq += redQ[k][c]; }
        float mean = ts * (1.f / Cdim);
        float var  = tq * (1.f / Cdim) - mean * mean;
        stats[c][0] = mean;
        stats[c][1] = rsqrtf(var + 1e-5f);
    }
    __syncthreads();

    float gg = lng[c], bb = lnb[c];
#pragma unroll
    for (int jt = 0; jt < TJ; jt++) {
        size_t idx = ((size_t)b * Ntok + i * 28 + j0 + jt) * Cdim + c;
        float v = val[jt];
        y[idx] = v;
        yln[idx] = __float2bfloat16((v - stats[jt][0]) * stats[jt][1] * gg + bb);
    }
}

// ---------------------------------------------------------------------------
// bf16 GEMM (R8 config: best measured).
// ---------------------------------------------------------------------------
#define BM 128
#define BN 128
#define BK 32
#define STAGES 3
#define ASTG (BM * 64)
#define STG_BYTES (2 * ASTG)

__device__ __forceinline__ void cp16(unsigned saddr, const void* g)
{
    asm volatile("cp.async.cg.shared.global [%0], [%1], 16;\n" :: "r"(saddr), "l"(g));
}
__device__ __forceinline__ void ldsm4(uint32_t& r0, uint32_t& r1, uint32_t& r2,
                                      uint32_t& r3, uint32_t a)
{
    asm volatile("ldmatrix.sync.aligned.m8n8.x4.shared.b16 {%0,%1,%2,%3}, [%4];"
                 : "=r"(r0), "=r"(r1), "=r"(r2), "=r"(r3) : "r"(a));
}

template<int EPI, int K>
__global__ __launch_bounds__(256, 2)
void gemm_bf16(const bf16* __restrict__ A, const bf16* __restrict__ W,
               const float* __restrict__ bias, const float* __restrict__ res,
               void* __restrict__ Cout, int M, int N)
{
    __shared__ alignas(128) char sm[STAGES * STG_BYTES];
    uint32_t sb = (uint32_t)__cvta_generic_to_shared(sm);

    int tid = threadIdx.x;
    int w = tid >> 5, l = tid & 31;
    int row0 = blockIdx.y * BM;
    int col0 = blockIdx.x * BN;
    int wm = (w & 1) * 64;
    int wn = (w >> 1) * 32;
    int g = l >> 2, t = l & 3;

    int jj  = l >> 3;
    int rlo = l & 7;
    int rowA_in = (jj & 1) * 8 + rlo;
    int cA = jj >> 1;
    uint32_t aoff[4], axr[4];
#pragma unroll
    for (int mi = 0; mi < 4; mi++) {
        int rA = wm + mi * 16 + rowA_in;
        aoff[mi] = (uint32_t)rA * 64;
        axr[mi]  = (uint32_t)(((rA >> 1) & 3) << 4);
    }
    int rowB_in = (jj >> 1) * 8 + rlo;
    int cB = jj & 1;
    uint32_t boff[2], bxr[2];
#pragma unroll
    for (int p = 0; p < 2; p++) {
        int rB = wn + p * 16 + rowB_in;
        boff[p] = (uint32_t)(ASTG + rB * 64);
        bxr[p]  = (uint32_t)(((rB >> 1) & 3) << 4);
    }

    float acc[4][4][4];
#pragma unroll
    for (int mi = 0; mi < 4; mi++)
#pragma unroll
        for (int ni = 0; ni < 4; ni++)
#pragma unroll
            for (int r = 0; r < 4; r++) acc[mi][ni][r] = 0.f;

    constexpr int NS = K / BK;

    auto load_stage = [&](int s) {
        uint32_t tb = sb + (s % STAGES) * STG_BYTES;
        int kt = s * BK;
        const bf16* Ab = A + (size_t)row0 * K + kt;
        const bf16* Wb = W + (size_t)col0 * K + kt;
#pragma unroll
        for (int i = 0; i < 2; i++) {
            int id = tid + i * 256;
            int r = id >> 2, c = id & 3;
            int cs = c ^ ((r >> 1) & 3);
            cp16(tb + r * 64 + cs * 16, Ab + (size_t)r * K + c * 8);
            cp16(tb + ASTG + r * 64 + cs * 16, Wb + (size_t)r * K + c * 8);
        }
    };

    load_stage(0);
    asm volatile("cp.async.commit_group;\n");
    load_stage(1);
    asm volatile("cp.async.commit_group;\n");

#pragma unroll
    for (int s = 0; s < NS; s++) {
        asm volatile("cp.async.wait_group 1;\n");
        __syncthreads();

        if (s + STAGES - 1 < NS) load_stage(s + STAGES - 1);
        asm volatile("cp.async.commit_group;\n");

        uint32_t stb = sb + (s % STAGES) * STG_BYTES;
#pragma unroll
        for (int kk = 0; kk < 2; kk++) {
            uint32_t c0 = kk * 2;
            uint32_t af[4][4], bq[2][4];
#pragma unroll
            for (int mi = 0; mi < 4; mi++)
                ldsm4(af[mi][0], af[mi][1], af[mi][2], af[mi][3],
                      stb + aoff[mi] + ((((c0 + cA) << 4)) ^ axr[mi]));
#pragma unroll
            for (int p = 0; p < 2; p++)
                ldsm4(bq[p][0], bq[p][1], bq[p][2], bq[p][3],
                      stb + boff[p] + ((((c0 + cB) << 4)) ^ bxr[p]));

#pragma unroll
            for (int mi = 0; mi < 4; mi++)
#pragma unroll
                for (int ni = 0; ni < 4; ni++) {
                    int p = ni >> 1, q = ni & 1;
                    asm volatile(
                        "mma.sync.aligned.m16n8k16.row.col.f32.bf16.bf16.f32 "
                        "{%0,%1,%2,%3}, {%4,%5,%6,%7}, {%8,%9}, {%0,%1,%2,%3};"
                        : "+f"(acc[mi][ni][0]), "+f"(acc[mi][ni][1]),
                          "+f"(acc[mi][ni][2]), "+f"(acc[mi][ni][3])
                        : "r"(af[mi][0]), "r"(af[mi][1]), "r"(af[mi][2]), "r"(af[mi][3]),
                          "r"(bq[p][2 * q]), "r"(bq[p][2 * q + 1]));
                }
        }
    }

#pragma unroll
    for (int mi = 0; mi < 4; mi++) {
#pragma unroll
        for (int ni = 0; ni < 4; ni++) {
            int col = col0 + wn + ni * 8 + 2 * t;
#pragma unroll
            for (int half = 0; half < 2; half++) {
                int row = row0 + wm + mi * 16 + g + half * 8;
                size_t idx = (size_t)row * N + col;
                float v0 = acc[mi][ni][2 * half];
                float v1 = acc[mi][ni][2 * half + 1];
                if (EPI == 0) {
                    *(float2*)&((float*)Cout)[idx] = make_float2(v0, v1);
                } else if (EPI == 2) {
                    float2 bv = *(const float2*)&bias[col];
                    v0 += bv.x; v1 += bv.y;
                    v0 = 0.5f * v0 * (1.f + erff(v0 * 0.7071067811865475f));
                    v1 = 0.5f * v1 * (1.f + erff(v1 * 0.7071067811865475f));
                    __nv_bfloat162 pk;
                    pk.x = __float2bfloat16(v0);
                    pk.y = __float2bfloat16(v1);
                    *(__nv_bfloat162*)&((bf16*)Cout)[idx] = pk;
                } else {
                    float2 bv = *(const float2*)&bias[col];
                    float2 rv = *(const float2*)&res[idx];
                    v0 += bv.x + rv.x; v1 += bv.y + rv.y;
                    *(float2*)&((float*)Cout)[idx] = make_float2(v0, v1);
                }
            }
        }
    }
}

// ---------------------------------------------------------------------------
// Channel attention stage A (R8 exact): per (bh, chunk) partial (k*s)^T v
// over 112 tokens, fully-unrolled 16-token sub-chunks, plain stores.
// ---------------------------------------------------------------------------
__global__ __launch_bounds__(256)
void attnA_partial(const float* __restrict__ qkv, float* __restrict__ partial)
{
    __shared__ float ks[16][49];
    __shared__ float vs[16][49];

    int bh = blockIdx.x;
    int b = bh >> 3, h = bh & 7;
    int chunk = blockIdx.y;
    int nstart = chunk * 112;
    int tid = threadIdx.x;
    int tx = tid & 15, ty = tid >> 4;
    const float scale = 0.14433756729740643f;   // 48^-0.5

    float acc[3][3] = {{0.f,0.f,0.f},{0.f,0.f,0.f},{0.f,0.f,0.f}};
    const float* base = qkv + (size_t)b * Ntok * H3 + h * HD;

    for (int n0 = nstart; n0 < nstart + 112; n0 += 16) {
#pragma unroll
        for (int it = 0; it < 3; it++) {
            int idx = tid + it * 256;
            int nn = idx / HD, d = idx - nn * HD;
            const float* r = base + (size_t)(n0 + nn) * H3;
            ks[nn][d] = r[Cdim + d] * scale;
            vs[nn][d] = r[2 * Cdim + d];
        }
        __syncthreads();
#pragma unroll
        for (int nn = 0; nn < 16; nn++) {
            float rk[3], rv[3];
#pragma unroll
            for (int i = 0; i < 3; i++) { rk[i] = ks[nn][ty * 3 + i]; rv[i] = vs[nn][tx * 3 + i]; }
#pragma unroll
            for (int i = 0; i < 3; i++)
#pragma unroll
                for (int j = 0; j < 3; j++)
                    acc[i][j] = fmaf(rk[i], rv[j], acc[i][j]);
        }
        __syncthreads();
    }

    float* o = partial + ((size_t)chunk * (Bsz * NH) + bh) * (HD * HD);
#pragma unroll
    for (int i = 0; i < 3; i++)
#pragma unroll
        for (int j = 0; j < 3; j++)
            o[(ty * 3 + i) * HD + tx * 3 + j] = acc[i][j];
}

// ---------------------------------------------------------------------------
// Fused softmax + attnB. One block per (b,h), 384 threads.
// 1) sum 7 partials into smem  2) row softmax (threads 0..47)
// 3) out[b,n,h*48+d] = sum_e attn[d,e]*q[b,n,h,e] over 56-token tiles,
//    attention row held in registers, q streamed via float4 LDS.
// All per-output FP op orders match the previous two-kernel version exactly.
// ---------------------------------------------------------------------------
__global__ __launch_bounds__(384)
void attnBF_kernel(const float* __restrict__ qkv, const float* __restrict__ partial,
                   bf16* __restrict__ out)
{
    __shared__ float at[HD * HD];        // stride 48, 16B-aligned rows
    __shared__ float qs[56][HD];

    int bh = blockIdx.x;
    int b = bh >> 3, h = bh & 7;
    int tid = threadIdx.x;

    // 1) sum partials (2304 entries / 384 threads = 6 each)
#pragma unroll
    for (int it = 0; it < 6; it++) {
        int idx = tid + it * 384;
        float s = 0.f;
#pragma unroll
        for (int ch = 0; ch < NCHUNK; ch++)
            s += partial[((size_t)ch * (Bsz * NH) + bh) * (HD * HD) + idx];
        at[idx] = s;
    }
    __syncthreads();

    // 2) softmax per row (threads 0..47), same op order as before
    if (tid < HD) {
        float* row = &at[tid * HD];
        float m = -1e30f;
#pragma unroll
        for (int e = 0; e < HD; e++) m = fmaxf(m, row[e]);
        float s = 0.f;
#pragma unroll
        for (int e = 0; e < HD; e++) { float tv = expf(row[e] - m); row[e] = tv; s += tv; }
        float inv = 1.f / s;
#pragma unroll
        for (int e = 0; e < HD; e++) row[e] *= inv;
    }
    __syncthreads();

    // 3) attention row -> registers (fixed d per thread)
    int nl = tid / HD;            // 0..7
    int d  = tid - nl * HD;       // 0..47
    float4 arow[12];
#pragma unroll
    for (int e4 = 0; e4 < 12; e4++)
        arow[e4] = *(float4*)&at[d * HD + e4 * 4];

    const float* qb = qkv + (size_t)b * Ntok * H3 + h * HD + d;
    bf16* ob = out + (size_t)b * Ntok * Cdim + h * HD + d;

    for (int n0 = 0; n0 < Ntok; n0 += 56) {      // 14 tiles exactly
#pragma unroll
        for (int r = 0; r < 7; r++)
            qs[nl + 8 * r][d] = qb[(size_t)(n0 + nl + 8 * r) * H3];
        __syncthreads();

        float acc[7] = {0.f, 0.f, 0.f, 0.f, 0.f, 0.f, 0.f};
#pragma unroll
        for (int e4 = 0; e4 < 12; e4++) {
            float4 ar = arow[e4];
#pragma unroll
            for (int r = 0; r < 7; r++) {
                float4 qv = *(float4*)&qs[nl + 8 * r][e4 * 4];
                acc[r] = fmaf(ar.x, qv.x, acc[r]);
                acc[r] = fmaf(ar.y, qv.y, acc[r]);
                acc[r] = fmaf(ar.z, qv.z, acc[r]);
                acc[r] = fmaf(ar.w, qv.w, acc[r]);
            }
        }
#pragma unroll
        for (int r = 0; r < 7; r++)
            ob[(size_t)(n0 + nl + 8 * r) * Cdim] = __float2bfloat16(acc[r]);
        __syncthreads();
    }
}

// ---------------------------------------------------------------------------
// Launch
// ---------------------------------------------------------------------------
extern "C" void kernel_launch(void* const* d_in, const int* in_sizes, int n_in,
                              void* d_out, int out_size)
{
    const float* x       = (const float*)d_in[0];
    const float* cpe0_w  = (const float*)d_in[3];
    const float* cpe0_b  = (const float*)d_in[4];
    const float* cpe1_w  = (const float*)d_in[5];
    const float* cpe1_b  = (const float*)d_in[6];
    const float* norm1_g = (const float*)d_in[7];
    const float* norm1_b = (const float*)d_in[8];
    const float* qkv_w   = (const float*)d_in[9];
    const float* proj_w  = (const float*)d_in[10];
    const float* proj_b  = (const float*)d_in[11];
    const float* norm2_g = (const float*)d_in[12];
    const float* norm2_b = (const float*)d_in[13];
    const float* fc1_w   = (const float*)d_in[14];
    const float* fc1_b   = (const float*)d_in[15];
    const float* fc2_w   = (const float*)d_in[16];
    const float* fc2_b   = (const float*)d_in[17];
    float* out = (float*)d_out;

    float *xa, *qkvb, *attn, *xb;
    bf16 *ln, *att, *hbuf, *wbf;
    cudaGetSymbolAddress((void**)&xa,    g_xa);
    cudaGetSymbolAddress((void**)&ln,    g_ln);
    cudaGetSymbolAddress((void**)&qkvb,  g_qkv);
    cudaGetSymbolAddress((void**)&attn,  g_attn);
    cudaGetSymbolAddress((void**)&att,   g_att);
    cudaGetSymbolAddress((void**)&xb,    g_xb);
    cudaGetSymbolAddress((void**)&hbuf,  g_h);
    cudaGetSymbolAddress((void**)&wbf,   g_wbf);

    dim3 cpeGrid(4, 28, Bsz);

    // one launch: convert all weights to bf16
    cvt_all_kernel<<<(W_TOT + 255) / 256, 256>>>(qkv_w, proj_w, fc1_w, fc2_w, wbf);

    // xa = cpe0(x); ln = LN1(xa) [bf16]
    cpe_ln_kernel<<<cpeGrid, Cdim>>>(x, cpe0_w, cpe0_b, norm1_g, norm1_b, xa, ln);
    // qkv = ln1 @ qkv_w^T  (fp32 out)
    gemm_bf16<0, Cdim><<<dim3(H3 / BN, NT / BM), 256>>>(ln, wbf + W_QKV, nullptr, nullptr, qkvb, NT, H3);
    // channel attention
    attnA_partial<<<dim3(Bsz * NH, NCHUNK), 256>>>(qkvb, attn);
    attnBF_kernel<<<Bsz * NH, 384>>>(qkvb, attn, att);
    // xb = xa + att @ proj_w^T + proj_b  (fp32 out)
    gemm_bf16<3, Cdim><<<dim3(Cdim / BN, NT / BM), 256>>>(att, wbf + W_PROJ, proj_b, xa, xb, NT, Cdim);
    // xc = cpe1(xb) -> xa ; ln = LN2(xc) [bf16]
    cpe_ln_kernel<<<cpeGrid, Cdim>>>(xb, cpe1_w, cpe1_b, norm2_g, norm2_b, xa, ln);
    // h = gelu(ln2 @ fc1^T + b1) [bf16 out]
    gemm_bf16<2, Cdim><<<dim3(HID / BN, NT / BM), 256>>>(ln, wbf + W_FC1, fc1_b, nullptr, hbuf, NT, HID);
    // out = xc + h @ fc2^T + b2 (fp32 out)
    gemm_bf16<3, HID><<<dim3(Cdim / BN, NT / BM), 256>>>(hbuf, wbf + W_FC2, fc2_b, xa, out, NT, Cdim);
}

// round 11
// speedup vs baseline: 1.2515x; 1.0133x over previous
#include <cuda_runtime.h>
#include <cuda_bf16.h>
#include <math.h>
#include <stdint.h>

// ---------------------------------------------------------------------------
// ChannelBlock: B=32, N=784 (28x28), C=384, heads=8, hd=48, MLP hidden=1536
// bf16 mma.sync GEMMs (R8 config), tiled cpe_ln, float4-tiled attnA,
// fused softmax+attnB (R10).
// ---------------------------------------------------------------------------

#define Bsz   32
#define Ntok  784
#define Cdim  384
#define NT    (Bsz * Ntok)     // 25088
#define H3    (3 * Cdim)       // 1152
#define HID   1536
#define NH    8
#define HD    48
#define NCHUNK 7               // attnA token chunks (112 each)

typedef __nv_bfloat16 bf16;

// scratch (static device memory; no allocation anywhere)
__device__ float g_xa  [(size_t)NT * Cdim];
__device__ bf16  g_ln  [(size_t)NT * Cdim];
__device__ float g_qkv [(size_t)NT * H3];
__device__ float g_attn[(size_t)NCHUNK * Bsz * NH * HD * HD];  // partial logits
__device__ bf16  g_att [(size_t)NT * Cdim];
__device__ float g_xb  [(size_t)NT * Cdim];
__device__ bf16  g_h   [(size_t)NT * HID];
// bf16 weights: qkv | proj | fc1 | fc2
#define W_QKV 0
#define W_PROJ (H3 * Cdim)
#define W_FC1  (W_PROJ + Cdim * Cdim)
#define W_FC2  (W_FC1 + HID * Cdim)
#define W_TOT  (W_FC2 + Cdim * HID)
__device__ bf16  g_wbf [(size_t)W_TOT];

// single launch: convert all 4 weight matrices to bf16
__global__ void cvt_all_kernel(const float* __restrict__ qkv_w,
                               const float* __restrict__ proj_w,
                               const float* __restrict__ fc1_w,
                               const float* __restrict__ fc2_w,
                               bf16* __restrict__ out)
{
    int i = blockIdx.x * blockDim.x + threadIdx.x;
    if (i >= W_TOT) return;
    float v;
    if (i < W_PROJ)      v = qkv_w[i];
    else if (i < W_FC1)  v = proj_w[i - W_PROJ];
    else if (i < W_FC2)  v = fc1_w[i - W_FC1];
    else                 v = fc2_w[i - W_FC2];
    out[i] = __float2bfloat16(v);
}

// ---------------------------------------------------------------------------
// Tiled fused cpe + LN (R8).
// ---------------------------------------------------------------------------
#define TJ 7
__global__ __launch_bounds__(Cdim)
void cpe_ln_kernel(const float* __restrict__ x,
                   const float* __restrict__ w,
                   const float* __restrict__ bias,
                   const float* __restrict__ lng,
                   const float* __restrict__ lnb,
                   float* __restrict__ y,
                   bf16* __restrict__ yln)
{
    __shared__ float tile[3][TJ + 2][Cdim];
    __shared__ float redS[12][TJ], redQ[12][TJ];
    __shared__ float stats[TJ][2];

    int c  = threadIdx.x;
    int jg = blockIdx.x;
    int i  = blockIdx.y;
    int b  = blockIdx.z;
    int j0 = jg * TJ;

    const float* xb = x + (size_t)b * Ntok * Cdim;

#pragma unroll
    for (int s = 0; s < 3 * (TJ + 2); s++) {
        int ri = s / (TJ + 2) + i - 1;
        int cj = s % (TJ + 2) + j0 - 1;
        float v = 0.f;
        if (ri >= 0 && ri < 28 && cj >= 0 && cj < 28)
            v = xb[(size_t)(ri * 28 + cj) * Cdim + c];
        tile[s / (TJ + 2)][s % (TJ + 2)][c] = v;
    }
    __syncthreads();

    const float* wc = w + c * 9;
    float wr[9];
#pragma unroll
    for (int q = 0; q < 9; q++) wr[q] = wc[q];
    float bs = bias[c];

    float val[TJ];
#pragma unroll
    for (int jt = 0; jt < TJ; jt++) {
        float acc = bs;
#pragma unroll
        for (int di = 0; di < 3; di++)
#pragma unroll
            for (int dj = 0; dj < 3; dj++)
                acc += wr[di * 3 + dj] * tile[di][jt + dj][c];
        val[jt] = tile[1][1 + jt][c] + acc;
    }

    int warp = c >> 5, lane = c & 31;
#pragma unroll
    for (int jt = 0; jt < TJ; jt++) {
        float s = val[jt], q = val[jt] * val[jt];
#pragma unroll
        for (int o = 16; o; o >>= 1) {
            s += __shfl_xor_sync(0xffffffffu, s, o);
            q += __shfl_xor_sync(0xffffffffu, q, o);
        }
        if (lane == 0) { redS[warp][jt] = s; redQ[warp][jt] = q; }
    }
    __syncthreads();
    if (c < TJ) {
        float ts = 0.f, tq = 0.f;
#pragma unroll
        for (int k = 0; k < 12; k++) { ts += redS[k][c]; tq += redQ[k][c]; }
        float mean = ts * (1.f / Cdim);
        float var  = tq * (1.f / Cdim) - mean * mean;
        stats[c][0] = mean;
        stats[c][1] = rsqrtf(var + 1e-5f);
    }
    __syncthreads();

    float gg = lng[c], bb = lnb[c];
#pragma unroll
    for (int jt = 0; jt < TJ; jt++) {
        size_t idx = ((size_t)b * Ntok + i * 28 + j0 + jt) * Cdim + c;
        float v = val[jt];
        y[idx] = v;
        yln[idx] = __float2bfloat16((v - stats[jt][0]) * stats[jt][1] * gg + bb);
    }
}

// ---------------------------------------------------------------------------
// bf16 GEMM (R8 config: best measured).
// ---------------------------------------------------------------------------
#define BM 128
#define BN 128
#define BK 32
#define STAGES 3
#define ASTG (BM * 64)
#define STG_BYTES (2 * ASTG)

__device__ __forceinline__ void cp16(unsigned saddr, const void* g)
{
    asm volatile("cp.async.cg.shared.global [%0], [%1], 16;\n" :: "r"(saddr), "l"(g));
}
__device__ __forceinline__ void ldsm4(uint32_t& r0, uint32_t& r1, uint32_t& r2,
                                      uint32_t& r3, uint32_t a)
{
    asm volatile("ldmatrix.sync.aligned.m8n8.x4.shared.b16 {%0,%1,%2,%3}, [%4];"
                 : "=r"(r0), "=r"(r1), "=r"(r2), "=r"(r3) : "r"(a));
}

template<int EPI, int K>
__global__ __launch_bounds__(256, 2)
void gemm_bf16(const bf16* __restrict__ A, const bf16* __restrict__ W,
               const float* __restrict__ bias, const float* __restrict__ res,
               void* __restrict__ Cout, int M, int N)
{
    __shared__ alignas(128) char sm[STAGES * STG_BYTES];
    uint32_t sb = (uint32_t)__cvta_generic_to_shared(sm);

    int tid = threadIdx.x;
    int w = tid >> 5, l = tid & 31;
    int row0 = blockIdx.y * BM;
    int col0 = blockIdx.x * BN;
    int wm = (w & 1) * 64;
    int wn = (w >> 1) * 32;
    int g = l >> 2, t = l & 3;

    int jj  = l >> 3;
    int rlo = l & 7;
    int rowA_in = (jj & 1) * 8 + rlo;
    int cA = jj >> 1;
    uint32_t aoff[4], axr[4];
#pragma unroll
    for (int mi = 0; mi < 4; mi++) {
        int rA = wm + mi * 16 + rowA_in;
        aoff[mi] = (uint32_t)rA * 64;
        axr[mi]  = (uint32_t)(((rA >> 1) & 3) << 4);
    }
    int rowB_in = (jj >> 1) * 8 + rlo;
    int cB = jj & 1;
    uint32_t boff[2], bxr[2];
#pragma unroll
    for (int p = 0; p < 2; p++) {
        int rB = wn + p * 16 + rowB_in;
        boff[p] = (uint32_t)(ASTG + rB * 64);
        bxr[p]  = (uint32_t)(((rB >> 1) & 3) << 4);
    }

    float acc[4][4][4];
#pragma unroll
    for (int mi = 0; mi < 4; mi++)
#pragma unroll
        for (int ni = 0; ni < 4; ni++)
#pragma unroll
            for (int r = 0; r < 4; r++) acc[mi][ni][r] = 0.f;

    constexpr int NS = K / BK;

    auto load_stage = [&](int s) {
        uint32_t tb = sb + (s % STAGES) * STG_BYTES;
        int kt = s * BK;
        const bf16* Ab = A + (size_t)row0 * K + kt;
        const bf16* Wb = W + (size_t)col0 * K + kt;
#pragma unroll
        for (int i = 0; i < 2; i++) {
            int id = tid + i * 256;
            int r = id >> 2, c = id & 3;
            int cs = c ^ ((r >> 1) & 3);
            cp16(tb + r * 64 + cs * 16, Ab + (size_t)r * K + c * 8);
            cp16(tb + ASTG + r * 64 + cs * 16, Wb + (size_t)r * K + c * 8);
        }
    };

    load_stage(0);
    asm volatile("cp.async.commit_group;\n");
    load_stage(1);
    asm volatile("cp.async.commit_group;\n");

#pragma unroll
    for (int s = 0; s < NS; s++) {
        asm volatile("cp.async.wait_group 1;\n");
        __syncthreads();

        if (s + STAGES - 1 < NS) load_stage(s + STAGES - 1);
        asm volatile("cp.async.commit_group;\n");

        uint32_t stb = sb + (s % STAGES) * STG_BYTES;
#pragma unroll
        for (int kk = 0; kk < 2; kk++) {
            uint32_t c0 = kk * 2;
            uint32_t af[4][4], bq[2][4];
#pragma unroll
            for (int mi = 0; mi < 4; mi++)
                ldsm4(af[mi][0], af[mi][1], af[mi][2], af[mi][3],
                      stb + aoff[mi] + ((((c0 + cA) << 4)) ^ axr[mi]));
#pragma unroll
            for (int p = 0; p < 2; p++)
                ldsm4(bq[p][0], bq[p][1], bq[p][2], bq[p][3],
                      stb + boff[p] + ((((c0 + cB) << 4)) ^ bxr[p]));

#pragma unroll
            for (int mi = 0; mi < 4; mi++)
#pragma unroll
                for (int ni = 0; ni < 4; ni++) {
                    int p = ni >> 1, q = ni & 1;
                    asm volatile(
                        "mma.sync.aligned.m16n8k16.row.col.f32.bf16.bf16.f32 "
                        "{%0,%1,%2,%3}, {%4,%5,%6,%7}, {%8,%9}, {%0,%1,%2,%3};"
                        : "+f"(acc[mi][ni][0]), "+f"(acc[mi][ni][1]),
                          "+f"(acc[mi][ni][2]), "+f"(acc[mi][ni][3])
                        : "r"(af[mi][0]), "r"(af[mi][1]), "r"(af[mi][2]), "r"(af[mi][3]),
                          "r"(bq[p][2 * q]), "r"(bq[p][2 * q + 1]));
                }
        }
    }

#pragma unroll
    for (int mi = 0; mi < 4; mi++) {
#pragma unroll
        for (int ni = 0; ni < 4; ni++) {
            int col = col0 + wn + ni * 8 + 2 * t;
#pragma unroll
            for (int half = 0; half < 2; half++) {
                int row = row0 + wm + mi * 16 + g + half * 8;
                size_t idx = (size_t)row * N + col;
                float v0 = acc[mi][ni][2 * half];
                float v1 = acc[mi][ni][2 * half + 1];
                if (EPI == 0) {
                    *(float2*)&((float*)Cout)[idx] = make_float2(v0, v1);
                } else if (EPI == 2) {
                    float2 bv = *(const float2*)&bias[col];
                    v0 += bv.x; v1 += bv.y;
                    v0 = 0.5f * v0 * (1.f + erff(v0 * 0.7071067811865475f));
                    v1 = 0.5f * v1 * (1.f + erff(v1 * 0.7071067811865475f));
                    __nv_bfloat162 pk;
                    pk.x = __float2bfloat16(v0);
                    pk.y = __float2bfloat16(v1);
                    *(__nv_bfloat162*)&((bf16*)Cout)[idx] = pk;
                } else {
                    float2 bv = *(const float2*)&bias[col];
                    float2 rv = *(const float2*)&res[idx];
                    v0 += bv.x + rv.x; v1 += bv.y + rv.y;
                    *(float2*)&((float*)Cout)[idx] = make_float2(v0, v1);
                }
            }
        }
    }
}

// ---------------------------------------------------------------------------
// Channel attention stage A: per (bh, chunk) partial (k*s)^T v over 112 tokens.
// 144 threads = 12x12 grid of 4x4 thread tiles; float4 fragment LDS.
// Per-output fmaf chain (ascending n) identical to R10 -> bit-identical.
// ---------------------------------------------------------------------------
#define ATHR 144
#define KVS  56    // padded row stride (floats), 16B aligned
__global__ __launch_bounds__(ATHR)
void attnA_partial(const float* __restrict__ qkv, float* __restrict__ partial)
{
    __shared__ float ks[16][KVS];
    __shared__ float vs[16][KVS];

    int bh = blockIdx.x;
    int b = bh >> 3, h = bh & 7;
    int chunk = blockIdx.y;
    int nstart = chunk * 112;
    int tid = threadIdx.x;
    int tx = tid % 12, ty = tid / 12;     // 12 x 12 tile grid
    const float scale = 0.14433756729740643f;   // 48^-0.5

    float acc[4][4];
#pragma unroll
    for (int i = 0; i < 4; i++)
#pragma unroll
        for (int j = 0; j < 4; j++) acc[i][j] = 0.f;

    const float* base = qkv + (size_t)b * Ntok * H3 + h * HD;

    for (int n0 = nstart; n0 < nstart + 112; n0 += 16) {
        // load 16 tokens x 48 d for k and v (768 elems each, 144 threads)
#pragma unroll
        for (int it = 0; it < 6; it++) {
            int idx = tid + it * ATHR;
            if (idx < 16 * HD) {
                int nn = idx / HD, d = idx - nn * HD;
                const float* r = base + (size_t)(n0 + nn) * H3;
                ks[nn][d] = r[Cdim + d] * scale;
                vs[nn][d] = r[2 * Cdim + d];
            }
        }
        __syncthreads();
#pragma unroll
        for (int nn = 0; nn < 16; nn++) {
            float4 rk = *(const float4*)&ks[nn][ty * 4];
            float4 rv = *(const float4*)&vs[nn][tx * 4];
            float k[4] = {rk.x, rk.y, rk.z, rk.w};
            float v[4] = {rv.x, rv.y, rv.z, rv.w};
#pragma unroll
            for (int i = 0; i < 4; i++)
#pragma unroll
                for (int j = 0; j < 4; j++)
                    acc[i][j] = fmaf(k[i], v[j], acc[i][j]);
        }
        __syncthreads();
    }

    float* o = partial + ((size_t)chunk * (Bsz * NH) + bh) * (HD * HD);
#pragma unroll
    for (int i = 0; i < 4; i++) {
        float4 st = make_float4(acc[i][0], acc[i][1], acc[i][2], acc[i][3]);
        *(float4*)&o[(ty * 4 + i) * HD + tx * 4] = st;
    }
}

// ---------------------------------------------------------------------------
// Fused softmax + attnB (R10). One block per (b,h), 384 threads.
// ---------------------------------------------------------------------------
__global__ __launch_bounds__(384)
void attnBF_kernel(const float* __restrict__ qkv, const float* __restrict__ partial,
                   bf16* __restrict__ out)
{
    __shared__ float at[HD * HD];
    __shared__ float qs[56][HD];

    int bh = blockIdx.x;
    int b = bh >> 3, h = bh & 7;
    int tid = threadIdx.x;

#pragma unroll
    for (int it = 0; it < 6; it++) {
        int idx = tid + it * 384;
        float s = 0.f;
#pragma unroll
        for (int ch = 0; ch < NCHUNK; ch++)
            s += partial[((size_t)ch * (Bsz * NH) + bh) * (HD * HD) + idx];
        at[idx] = s;
    }
    __syncthreads();

    if (tid < HD) {
        float* row = &at[tid * HD];
        float m = -1e30f;
#pragma unroll
        for (int e = 0; e < HD; e++) m = fmaxf(m, row[e]);
        float s = 0.f;
#pragma unroll
        for (int e = 0; e < HD; e++) { float tv = expf(row[e] - m); row[e] = tv; s += tv; }
        float inv = 1.f / s;
#pragma unroll
        for (int e = 0; e < HD; e++) row[e] *= inv;
    }
    __syncthreads();

    int nl = tid / HD;
    int d  = tid - nl * HD;
    float4 arow[12];
#pragma unroll
    for (int e4 = 0; e4 < 12; e4++)
        arow[e4] = *(float4*)&at[d * HD + e4 * 4];

    const float* qb = qkv + (size_t)b * Ntok * H3 + h * HD + d;
    bf16* ob = out + (size_t)b * Ntok * Cdim + h * HD + d;

    for (int n0 = 0; n0 < Ntok; n0 += 56) {
#pragma unroll
        for (int r = 0; r < 7; r++)
            qs[nl + 8 * r][d] = qb[(size_t)(n0 + nl + 8 * r) * H3];
        __syncthreads();

        float acc[7] = {0.f, 0.f, 0.f, 0.f, 0.f, 0.f, 0.f};
#pragma unroll
        for (int e4 = 0; e4 < 12; e4++) {
            float4 ar = arow[e4];
#pragma unroll
            for (int r = 0; r < 7; r++) {
                float4 qv = *(float4*)&qs[nl + 8 * r][e4 * 4];
                acc[r] = fmaf(ar.x, qv.x, acc[r]);
                acc[r] = fmaf(ar.y, qv.y, acc[r]);
                acc[r] = fmaf(ar.z, qv.z, acc[r]);
                acc[r] = fmaf(ar.w, qv.w, acc[r]);
            }
        }
#pragma unroll
        for (int r = 0; r < 7; r++)
            ob[(size_t)(n0 + nl + 8 * r) * Cdim] = __float2bfloat16(acc[r]);
        __syncthreads();
    }
}

// ---------------------------------------------------------------------------
// Launch
// ---------------------------------------------------------------------------
extern "C" void kernel_launch(void* const* d_in, const int* in_sizes, int n_in,
                              void* d_out, int out_size)
{
    const float* x       = (const float*)d_in[0];
    const float* cpe0_w  = (const float*)d_in[3];
    const float* cpe0_b  = (const float*)d_in[4];
    const float* cpe1_w  = (const float*)d_in[5];
    const float* cpe1_b  = (const float*)d_in[6];
    const float* norm1_g = (const float*)d_in[7];
    const float* norm1_b = (const float*)d_in[8];
    const float* qkv_w   = (const float*)d_in[9];
    const float* proj_w  = (const float*)d_in[10];
    const float* proj_b  = (const float*)d_in[11];
    const float* norm2_g = (const float*)d_in[12];
    const float* norm2_b = (const float*)d_in[13];
    const float* fc1_w   = (const float*)d_in[14];
    const float* fc1_b   = (const float*)d_in[15];
    const float* fc2_w   = (const float*)d_in[16];
    const float* fc2_b   = (const float*)d_in[17];
    float* out = (float*)d_out;

    float *xa, *qkvb, *attn, *xb;
    bf16 *ln, *att, *hbuf, *wbf;
    cudaGetSymbolAddress((void**)&xa,    g_xa);
    cudaGetSymbolAddress((void**)&ln,    g_ln);
    cudaGetSymbolAddress((void**)&qkvb,  g_qkv);
    cudaGetSymbolAddress((void**)&attn,  g_attn);
    cudaGetSymbolAddress((void**)&att,   g_att);
    cudaGetSymbolAddress((void**)&xb,    g_xb);
    cudaGetSymbolAddress((void**)&hbuf,  g_h);
    cudaGetSymbolAddress((void**)&wbf,   g_wbf);

    dim3 cpeGrid(4, 28, Bsz);

    // one launch: convert all weights to bf16
    cvt_all_kernel<<<(W_TOT + 255) / 256, 256>>>(qkv_w, proj_w, fc1_w, fc2_w, wbf);

    // xa = cpe0(x); ln = LN1(xa) [bf16]
    cpe_ln_kernel<<<cpeGrid, Cdim>>>(x, cpe0_w, cpe0_b, norm1_g, norm1_b, xa, ln);
    // qkv = ln1 @ qkv_w^T  (fp32 out)
    gemm_bf16<0, Cdim><<<dim3(H3 / BN, NT / BM), 256>>>(ln, wbf + W_QKV, nullptr, nullptr, qkvb, NT, H3);
    // channel attention
    attnA_partial<<<dim3(Bsz * NH, NCHUNK), ATHR>>>(qkvb, attn);
    attnBF_kernel<<<Bsz * NH, 384>>>(qkvb, attn, att);
    // xb = xa + att @ proj_w^T + proj_b  (fp32 out)
    gemm_bf16<3, Cdim><<<dim3(Cdim / BN, NT / BM), 256>>>(att, wbf + W_PROJ, proj_b, xa, xb, NT, Cdim);
    // xc = cpe1(xb) -> xa ; ln = LN2(xc) [bf16]
    cpe_ln_kernel<<<cpeGrid, Cdim>>>(xb, cpe1_w, cpe1_b, norm2_g, norm2_b, xa, ln);
    // h = gelu(ln2 @ fc1^T + b1) [bf16 out]
    gemm_bf16<2, Cdim><<<dim3(HID / BN, NT / BM), 256>>>(ln, wbf + W_FC1, fc1_b, nullptr, hbuf, NT, HID);
    // out = xc + h @ fc2^T + b2 (fp32 out)
    gemm_bf16<3, HID><<<dim3(Cdim / BN, NT / BM), 256>>>(hbuf, wbf + W_FC2, fc2_b, xa, out, NT, Cdim);
}